// round 14
// baseline (speedup 1.0000x reference)
#include <cuda_runtime.h>
#include <cuda_bf16.h>
#include <cstdint>

// LinearAttention: out[n,l,h,e] = (phi(Q)@KV) * Z, phi = elu+1 (vlen cancels)
//   KV = sum_s phi(K)[s,d] * V[s,e] ;  Z = 1/(phi(Q).Ksum + 1e-6)
//
// R14: bandwidth duty-cycle push. p2: 4 l-tiles/CTA with rolling register
// prefetch (loads in flight during every compute phase). Streaming cache
// hints (__ldcs/__stcs) on all single-use streams. p1/reduce = R12 + __ldcs.

#define DEV_INLINE __device__ __forceinline__

constexpr int Hh = 8, Dd = 64, Ll = 8192, Ss = 8192, Nn = 4;
constexpr int NH = Nn * Hh;                // 32
constexpr int ROWSTRIDE = Hh * Dd;         // 512
constexpr int P1_CHUNKS = 16;
constexpr int P1_SCHUNK = Ss / P1_CHUNKS;  // 512 s per CTA (8 tiles of 64)
constexpr int P1_NT = P1_SCHUNK / 64;      // 8

__device__ __align__(16) float g_part_kv[(size_t)P1_CHUNKS * NH * 4096]; // [e][d]
__device__ __align__(16) float g_part_ks[P1_CHUNKS * NH * 64];
__device__ __align__(16) float g_kv[NH * 4096];   // [nh][e][d]
__device__ __align__(16) float g_ks[NH * 64];

using u64 = unsigned long long;

DEV_INLINE float featmap(float x) { return __expf(fminf(x, 0.f)) + fmaxf(x, 0.f); }
DEV_INLINE unsigned bf2u(__nv_bfloat162 v) { return *reinterpret_cast<unsigned*>(&v); }
DEV_INLINE void bsplit2(float a, float b, unsigned& h, unsigned& l) {
    __nv_bfloat162 hv = __floats2bfloat162_rn(a, b);
    float2 hf = __bfloat1622float2(hv);
    __nv_bfloat162 lv = __floats2bfloat162_rn(a - hf.x, b - hf.y);
    h = bf2u(hv); l = bf2u(lv);
}
DEV_INLINE uint32_t smem_u32(const void* p) {
    uint32_t a;
    asm("{ .reg .u64 t; cvta.to.shared.u64 t, %1; cvt.u32.u64 %0, t; }"
        : "=r"(a) : "l"(p));
    return a;
}
DEV_INLINE void mma_bf16(float4& c, const uint32_t a[4], uint32_t b0, uint32_t b1) {
    asm volatile(
        "mma.sync.aligned.m16n8k16.row.col.f32.bf16.bf16.f32 "
        "{%0,%1,%2,%3}, {%4,%5,%6,%7}, {%8,%9}, {%0,%1,%2,%3};"
        : "+f"(c.x), "+f"(c.y), "+f"(c.z), "+f"(c.w)
        : "r"(a[0]), "r"(a[1]), "r"(a[2]), "r"(a[3]), "r"(b0), "r"(b1));
}
DEV_INLINE void ldm4t(uint32_t* r, uint32_t addr) {
    asm volatile(
        "ldmatrix.sync.aligned.m8n8.x4.trans.shared.b16 {%0,%1,%2,%3}, [%4];"
        : "=r"(r[0]), "=r"(r[1]), "=r"(r[2]), "=r"(r[3]) : "r"(addr));
}
DEV_INLINE void ldm2t(uint32_t* r, uint32_t addr) {
    asm volatile(
        "ldmatrix.sync.aligned.m8n8.x2.trans.shared.b16 {%0,%1}, [%2];"
        : "=r"(r[0]), "=r"(r[1]) : "r"(addr));
}

// ---- p1 smem: K/V hi/lo, each 2buf x 64 x 144B ----
constexpr uint32_t P1_KH = 0;
constexpr uint32_t P1_KL = 18432;
constexpr uint32_t P1_VH = 36864;
constexpr uint32_t P1_VL = 55296;
constexpr uint32_t P1_DSM = 73728;

// ============================================================================
// Phase 1 (R12-validated): D[e][d] = V^T @ phiK. 256 thr / 8 warps.
// wid: ki=wid&1, ni=(wid>>1)&1, mi=wid>>2. Cells: 2m x 4g. Grid (16, NH).
// ============================================================================
__global__ __launch_bounds__(256) void p1_kernel(const float* __restrict__ keys,
                                                 const float* __restrict__ values) {
    extern __shared__ __align__(16) char sm1[];

    const int t   = threadIdx.x;
    const int wid = t >> 5, lid = t & 31;
    const int grp = lid >> 3, r8 = lid & 7;
    const int qg  = lid >> 2, tg = lid & 3;
    const int nh  = blockIdx.y;
    const int n   = nh >> 3, h = nh & 7;
    const int s0  = blockIdx.x * P1_SCHUNK;
    const int ki  = wid & 1, ni = (wid >> 1) & 1, mi = wid >> 2;

    const uint32_t smb = smem_u32(sm1);
    const uint32_t aoff = (uint32_t)((r8 + ((grp & 2) ? 8 : 0)) * 144 +
                                     ((grp & 1) ? 8 : 0) * 2);
    const uint32_t boff = (uint32_t)((r8 + ((grp & 1) ? 8 : 0)) * 144);

    float4 acc[2][4];
#pragma unroll
    for (int i = 0; i < 2; i++)
#pragma unroll
        for (int j = 0; j < 4; j++) acc[i][j] = make_float4(0.f, 0.f, 0.f, 0.f);
    float4 ksum4 = make_float4(0.f, 0.f, 0.f, 0.f);

    const int c4 = t & 15, rbase = t >> 4;

    float4 bk[4], bv[4];
#pragma unroll
    for (int j = 0; j < 4; ++j) {
        size_t row = (size_t)(n * Ss + s0 + rbase + 16 * j);
        bk[j] = __ldcs((const float4*)(keys   + row * ROWSTRIDE + h * Dd + c4 * 4));
        bv[j] = __ldcs((const float4*)(values + row * ROWSTRIDE + h * Dd + c4 * 4));
    }

    for (int tile = 0; tile < P1_NT; ++tile) {
        const int b = tile & 1;
        char* KH = sm1 + P1_KH + b * 9216;
        char* KL = sm1 + P1_KL + b * 9216;
        char* VH = sm1 + P1_VH + b * 9216;
        char* VL = sm1 + P1_VL + b * 9216;
#pragma unroll
        for (int j = 0; j < 4; ++j) {
            const int sr = rbase + 16 * j;
            unsigned h0, l0_, h1, l1;
            float fx = featmap(bk[j].x), fy = featmap(bk[j].y);
            float fz = featmap(bk[j].z), fw = featmap(bk[j].w);
            ksum4.x += fx; ksum4.y += fy; ksum4.z += fz; ksum4.w += fw;
            bsplit2(fx, fy, h0, l0_);
            bsplit2(fz, fw, h1, l1);
            *(u64*)(KH + sr * 144 + c4 * 8) = ((u64)h1 << 32) | h0;
            *(u64*)(KL + sr * 144 + c4 * 8) = ((u64)l1 << 32) | l0_;
            bsplit2(bv[j].x, bv[j].y, h0, l0_);
            bsplit2(bv[j].z, bv[j].w, h1, l1);
            *(u64*)(VH + sr * 144 + c4 * 8) = ((u64)h1 << 32) | h0;
            *(u64*)(VL + sr * 144 + c4 * 8) = ((u64)l1 << 32) | l0_;
        }
        __syncthreads();

        if (tile + 1 < P1_NT) {
#pragma unroll
            for (int j = 0; j < 4; ++j) {
                size_t row = (size_t)(n * Ss + s0 + (tile + 1) * 64 + rbase + 16 * j);
                bk[j] = __ldcs((const float4*)(keys   + row * ROWSTRIDE + h * Dd + c4 * 4));
                bv[j] = __ldcs((const float4*)(values + row * ROWSTRIDE + h * Dd + c4 * 4));
            }
        }

        const uint32_t KHu = smb + P1_KH + b * 9216;
        const uint32_t KLu = smb + P1_KL + b * 9216;
        const uint32_t VHu = smb + P1_VH + b * 9216;
        const uint32_t VLu = smb + P1_VL + b * 9216;
#pragma unroll
        for (int k2 = 0; k2 < 2; ++k2) {
            const int kt = ki * 2 + k2;
            uint32_t ah[2][4], al[2][4];
#pragma unroll
            for (int m2 = 0; m2 < 2; ++m2) {
                const int mt = mi * 2 + m2;   // e-tile
                ldm4t(ah[m2], VHu + (uint32_t)(kt * 2304 + mt * 32) + aoff);
                ldm4t(al[m2], VLu + (uint32_t)(kt * 2304 + mt * 32) + aoff);
            }
#pragma unroll
            for (int g2 = 0; g2 < 4; ++g2) {
                const int gx = ni * 4 + g2;   // d-group (full coverage)
                uint32_t bh[2], bl[2];
                ldm2t(bh, KHu + (uint32_t)(kt * 2304 + gx * 16) + boff);
                ldm2t(bl, KLu + (uint32_t)(kt * 2304 + gx * 16) + boff);
#pragma unroll
                for (int m2 = 0; m2 < 2; ++m2) {
                    mma_bf16(acc[m2][g2], ah[m2], bh[0], bh[1]);
                    mma_bf16(acc[m2][g2], ah[m2], bl[0], bl[1]);
                    mma_bf16(acc[m2][g2], al[m2], bh[0], bh[1]);
                }
            }
        }
    }

    // ---- combine k-split pairs via smem; Ksum tree (dead-buffer scratch) ----
    __syncthreads();
    float* S    = (float*)(sm1 + P1_KH);      // 16 KB combine scratch
    float* scrK = (float*)(sm1 + P1_VH);      // 16x68 ksum scratch
    if (ki == 1) {
        const int j = wid >> 1;
#pragma unroll
        for (int m2 = 0; m2 < 2; ++m2)
#pragma unroll
            for (int g2 = 0; g2 < 4; ++g2) {
                const int cell = m2 * 4 + g2;
                *(float4*)(S + ((cell * 4 + j) * 32 + lid) * 4) = acc[m2][g2];
            }
    }
    *(float4*)(scrK + rbase * 68 + c4 * 4) = ksum4;
    __syncthreads();

    if (t < 64) {
        float s = 0.f;
#pragma unroll
        for (int r = 0; r < 16; ++r) s += scrK[r * 68 + t];
        g_part_ks[(blockIdx.x * NH + nh) * 64 + t] = s;
    }
    if (ki == 0) {
        const int j = wid >> 1;
        float* base = g_part_kv + ((size_t)blockIdx.x * NH + nh) * 4096;
#pragma unroll
        for (int m2 = 0; m2 < 2; ++m2)
#pragma unroll
            for (int g2 = 0; g2 < 4; ++g2) {
                const int cell = m2 * 4 + g2;
                float4 o = *(float4*)(S + ((cell * 4 + j) * 32 + lid) * 4);
                o.x += acc[m2][g2].x; o.y += acc[m2][g2].y;
                o.z += acc[m2][g2].z; o.w += acc[m2][g2].w;
                const int e0 = (mi * 2 + m2) * 16 + qg;
                const int d0 = (ni * 4 + g2) * 8 + tg * 2;
                *(float2*)(base + e0 * 64 + d0)       = make_float2(o.x, o.y);
                *(float2*)(base + (e0 + 8) * 64 + d0) = make_float2(o.z, o.w);
            }
    }
}

// ============================================================================
// Phase 1b: fixed-order reduction (16 slots)
// ============================================================================
__global__ void reduce_kernel() {
    int i = blockIdx.x * 256 + threadIdx.x;
    if (i < NH * 1024) {
        float4 s = make_float4(0.f, 0.f, 0.f, 0.f);
#pragma unroll
        for (int c = 0; c < P1_CHUNKS; c++) {
            float4 p = *(const float4*)(g_part_kv + (size_t)c * NH * 4096 + i * 4);
            s.x += p.x; s.y += p.y; s.z += p.z; s.w += p.w;
        }
        *(float4*)(g_kv + i * 4) = s;
    } else if (i < NH * 1024 + NH * 16) {
        int j = i - NH * 1024;
        float4 s = make_float4(0.f, 0.f, 0.f, 0.f);
#pragma unroll
        for (int c = 0; c < P1_CHUNKS; c++) {
            float4 p = *(const float4*)(g_part_ks + c * NH * 64 + j * 4);
            s.x += p.x; s.y += p.y; s.z += p.z; s.w += p.w;
        }
        *(float4*)(g_ks + j * 4) = s;
    }
}

// ---- p2 smem: B only (72 x 144B hi/lo) ----
constexpr uint32_t P2_BH = 0;
constexpr uint32_t P2_BL = 10368;
constexpr uint32_t P2_DSM = 20736;
constexpr int P2_TILES = 4;

// ============================================================================
// Phase 2: out = (phiQ @ KV_ext) * Z. 256 thr / 8 warps, warp = one m16
// l-tile, 9 n-tiles (Z = B row 64). A-fragments register-direct from gmem
// (__ldcs float2). 4 l-tiles/CTA, rolling 2-deep prefetch: tile t+1's loads
// are in flight during tile t's MMA. __stcs output. Grid (Ll/512, NH).
// ============================================================================
__global__ __launch_bounds__(256, 2) void p2_kernel(const float* __restrict__ queries,
                                                    float* __restrict__ out) {
    extern __shared__ __align__(16) char sm2[];
    char* BH = sm2 + P2_BH; char* BL = sm2 + P2_BL;

    const int t    = threadIdx.x;
    const int wid  = t >> 5, lane = t & 31;
    const int g    = lane >> 2, tg = lane & 3;
    const int nh   = blockIdx.y;
    const int n    = nh >> 3, h = nh & 7;
    const int lbase = blockIdx.x * (128 * P2_TILES);

    // stage B: rows 0..63 = g_kv[e][d], row 64 = g_ks (Ksum), 65..71 = 0
    if (t < 72) {
        const float* src = (t < 64) ? (g_kv + (size_t)nh * 4096 + t * 64)
                                    : (g_ks + nh * 64);
#pragma unroll
        for (int c = 0; c < 16; ++c) {
            float4 v = (t <= 64) ? *(const float4*)(src + c * 4)
                                 : make_float4(0.f, 0.f, 0.f, 0.f);
            unsigned hxy, lxy, hzw, lzw;
            bsplit2(v.x, v.y, hxy, lxy);
            bsplit2(v.z, v.w, hzw, lzw);
            *(u64*)(BH + t * 144 + c * 8) = ((u64)hzw << 32) | hxy;
            *(u64*)(BL + t * 144 + c * 8) = ((u64)lzw << 32) | lxy;
        }
    }

    const int r0 = wid * 16 + g;
    const float* qb = queries + ((size_t)(n * Ll + lbase) * ROWSTRIDE + h * Dd);

    float2 q[2][16];
    // prefetch tile 0
    {
        const float* rowp = qb + (size_t)r0 * ROWSTRIDE;
#pragma unroll
        for (int kt = 0; kt < 4; ++kt) {
            const int col = kt * 16 + tg * 2;
            q[0][kt * 4 + 0] = __ldcs((const float2*)(rowp + col));
            q[0][kt * 4 + 1] = __ldcs((const float2*)(rowp + 8 * ROWSTRIDE + col));
            q[0][kt * 4 + 2] = __ldcs((const float2*)(rowp + col + 8));
            q[0][kt * 4 + 3] = __ldcs((const float2*)(rowp + 8 * ROWSTRIDE + col + 8));
        }
    }
    __syncthreads();   // B staged

    for (int tile = 0; tile < P2_TILES; ++tile) {
        const int cur = tile & 1;
        // rolling prefetch: issue tile+1's loads before computing tile
        if (tile + 1 < P2_TILES) {
            const float* rowp = qb + (size_t)((tile + 1) * 128 + r0) * ROWSTRIDE;
#pragma unroll
            for (int kt = 0; kt < 4; ++kt) {
                const int col = kt * 16 + tg * 2;
                q[cur ^ 1][kt * 4 + 0] = __ldcs((const float2*)(rowp + col));
                q[cur ^ 1][kt * 4 + 1] = __ldcs((const float2*)(rowp + 8 * ROWSTRIDE + col));
                q[cur ^ 1][kt * 4 + 2] = __ldcs((const float2*)(rowp + col + 8));
                q[cur ^ 1][kt * 4 + 3] = __ldcs((const float2*)(rowp + 8 * ROWSTRIDE + col + 8));
            }
        }

        float4 C[9];
#pragma unroll
        for (int nt = 0; nt < 9; ++nt) C[nt] = make_float4(0.f, 0.f, 0.f, 0.f);

#pragma unroll
        for (int kt = 0; kt < 4; ++kt) {
            uint32_t ah[4], al[4];
#pragma unroll
            for (int j = 0; j < 4; ++j) {
                float2 v = q[cur][kt * 4 + j];
                bsplit2(featmap(v.x), featmap(v.y), ah[j], al[j]);
            }
            const int kb = kt * 32 + tg * 4;
#pragma unroll
            for (int nt = 0; nt < 9; ++nt) {
                const int e0 = nt * 8 + g;
                uint32_t bh0 = *(const uint32_t*)(BH + e0 * 144 + kb);
                uint32_t bh1 = *(const uint32_t*)(BH + e0 * 144 + kb + 16);
                uint32_t bl0 = *(const uint32_t*)(BL + e0 * 144 + kb);
                uint32_t bl1 = *(const uint32_t*)(BL + e0 * 144 + kb + 16);
                mma_bf16(C[nt], ah, bh0, bh1);
                mma_bf16(C[nt], ah, bl0, bl1);
                mma_bf16(C[nt], al, bh0, bh1);
            }
        }

        // epilogue: Z = C[8] col 0 (quad-leader lanes)
        const int src = (lane >> 2) << 2;
        float z0 = __shfl_sync(0xFFFFFFFFu, C[8].x, src);
        float z1 = __shfl_sync(0xFFFFFFFFu, C[8].z, src);
        float i0 = 1.0f / (z0 + 1e-6f);
        float i1 = 1.0f / (z1 + 1e-6f);
        const int row = lbase + tile * 128 + r0;
        float* p0 = out + ((size_t)(n * Ll + row) * Hh + h) * Dd;
        float* p1 = p0 + (size_t)8 * ROWSTRIDE;
#pragma unroll
        for (int nt = 0; nt < 8; ++nt) {
            const int col = nt * 8 + tg * 2;
            __stcs((float2*)(p0 + col), make_float2(C[nt].x * i0, C[nt].y * i0));
            __stcs((float2*)(p1 + col), make_float2(C[nt].z * i1, C[nt].w * i1));
        }
    }
}

// ============================================================================
extern "C" void kernel_launch(void* const* d_in, const int* in_sizes, int n_in,
                              void* d_out, int out_size) {
    const float* q = (const float*)d_in[0];
    const float* k = (const float*)d_in[1];
    const float* v = (const float*)d_in[2];
    float* o = (float*)d_out;
    (void)in_sizes; (void)n_in; (void)out_size;

    cudaFuncSetAttribute(p1_kernel, cudaFuncAttributeMaxDynamicSharedMemorySize, P1_DSM);
    cudaFuncSetAttribute(p2_kernel, cudaFuncAttributeMaxDynamicSharedMemorySize, P2_DSM);

    p1_kernel<<<dim3(P1_CHUNKS, NH), 256, P1_DSM>>>(k, v);
    reduce_kernel<<<(NH * 1024 + NH * 16 + 255) / 256, 256>>>();
    p2_kernel<<<dim3(Ll / (128 * P2_TILES), NH), 256, P2_DSM>>>(q, o);
}

// round 15
// speedup vs baseline: 1.0538x; 1.0538x over previous
#include <cuda_runtime.h>
#include <cuda_bf16.h>
#include <cstdint>

// LinearAttention: out[n,l,h,e] = (phi(Q)@KV) * Z, phi = elu+1 (vlen cancels)
//   KV = sum_s phi(K)[s,d] * V[s,e] ;  Z = 1/(phi(Q).Ksum + 1e-6)
//
// R15 = R13 (measured 86.0) + p2 rolling prefetch done right: 4 l-tiles/CTA,
// tile loop FULLY UNROLLED so the double-buffer index q[tile&1] is compile-
// time (R14's runtime-indexed buffer spilled to local -> regression).
// No cache hints. p1/reduce = R12-validated.

#define DEV_INLINE __device__ __forceinline__

constexpr int Hh = 8, Dd = 64, Ll = 8192, Ss = 8192, Nn = 4;
constexpr int NH = Nn * Hh;                // 32
constexpr int ROWSTRIDE = Hh * Dd;         // 512
constexpr int P1_CHUNKS = 16;
constexpr int P1_SCHUNK = Ss / P1_CHUNKS;  // 512 s per CTA (8 tiles of 64)
constexpr int P1_NT = P1_SCHUNK / 64;      // 8

__device__ __align__(16) float g_part_kv[(size_t)P1_CHUNKS * NH * 4096]; // [e][d]
__device__ __align__(16) float g_part_ks[P1_CHUNKS * NH * 64];
__device__ __align__(16) float g_kv[NH * 4096];   // [nh][e][d]
__device__ __align__(16) float g_ks[NH * 64];

using u64 = unsigned long long;

DEV_INLINE float featmap(float x) { return __expf(fminf(x, 0.f)) + fmaxf(x, 0.f); }
DEV_INLINE unsigned bf2u(__nv_bfloat162 v) { return *reinterpret_cast<unsigned*>(&v); }
DEV_INLINE void bsplit2(float a, float b, unsigned& h, unsigned& l) {
    __nv_bfloat162 hv = __floats2bfloat162_rn(a, b);
    float2 hf = __bfloat1622float2(hv);
    __nv_bfloat162 lv = __floats2bfloat162_rn(a - hf.x, b - hf.y);
    h = bf2u(hv); l = bf2u(lv);
}
DEV_INLINE uint32_t smem_u32(const void* p) {
    uint32_t a;
    asm("{ .reg .u64 t; cvta.to.shared.u64 t, %1; cvt.u32.u64 %0, t; }"
        : "=r"(a) : "l"(p));
    return a;
}
DEV_INLINE void mma_bf16(float4& c, const uint32_t a[4], uint32_t b0, uint32_t b1) {
    asm volatile(
        "mma.sync.aligned.m16n8k16.row.col.f32.bf16.bf16.f32 "
        "{%0,%1,%2,%3}, {%4,%5,%6,%7}, {%8,%9}, {%0,%1,%2,%3};"
        : "+f"(c.x), "+f"(c.y), "+f"(c.z), "+f"(c.w)
        : "r"(a[0]), "r"(a[1]), "r"(a[2]), "r"(a[3]), "r"(b0), "r"(b1));
}
DEV_INLINE void ldm4t(uint32_t* r, uint32_t addr) {
    asm volatile(
        "ldmatrix.sync.aligned.m8n8.x4.trans.shared.b16 {%0,%1,%2,%3}, [%4];"
        : "=r"(r[0]), "=r"(r[1]), "=r"(r[2]), "=r"(r[3]) : "r"(addr));
}
DEV_INLINE void ldm2t(uint32_t* r, uint32_t addr) {
    asm volatile(
        "ldmatrix.sync.aligned.m8n8.x2.trans.shared.b16 {%0,%1}, [%2];"
        : "=r"(r[0]), "=r"(r[1]) : "r"(addr));
}

// ---- p1 smem: K/V hi/lo, each 2buf x 64 x 144B ----
constexpr uint32_t P1_KH = 0;
constexpr uint32_t P1_KL = 18432;
constexpr uint32_t P1_VH = 36864;
constexpr uint32_t P1_VL = 55296;
constexpr uint32_t P1_DSM = 73728;

// ============================================================================
// Phase 1 (R12-validated, 39.1us): D[e][d] = V^T @ phiK. 256 thr / 8 warps.
// ============================================================================
__global__ __launch_bounds__(256) void p1_kernel(const float* __restrict__ keys,
                                                 const float* __restrict__ values) {
    extern __shared__ __align__(16) char sm1[];

    const int t   = threadIdx.x;
    const int wid = t >> 5, lid = t & 31;
    const int grp = lid >> 3, r8 = lid & 7;
    const int qg  = lid >> 2, tg = lid & 3;
    const int nh  = blockIdx.y;
    const int n   = nh >> 3, h = nh & 7;
    const int s0  = blockIdx.x * P1_SCHUNK;
    const int ki  = wid & 1, ni = (wid >> 1) & 1, mi = wid >> 2;

    const uint32_t smb = smem_u32(sm1);
    const uint32_t aoff = (uint32_t)((r8 + ((grp & 2) ? 8 : 0)) * 144 +
                                     ((grp & 1) ? 8 : 0) * 2);
    const uint32_t boff = (uint32_t)((r8 + ((grp & 1) ? 8 : 0)) * 144);

    float4 acc[2][4];
#pragma unroll
    for (int i = 0; i < 2; i++)
#pragma unroll
        for (int j = 0; j < 4; j++) acc[i][j] = make_float4(0.f, 0.f, 0.f, 0.f);
    float4 ksum4 = make_float4(0.f, 0.f, 0.f, 0.f);

    const int c4 = t & 15, rbase = t >> 4;

    float4 bk[4], bv[4];
#pragma unroll
    for (int j = 0; j < 4; ++j) {
        size_t row = (size_t)(n * Ss + s0 + rbase + 16 * j);
        bk[j] = *(const float4*)(keys   + row * ROWSTRIDE + h * Dd + c4 * 4);
        bv[j] = *(const float4*)(values + row * ROWSTRIDE + h * Dd + c4 * 4);
    }

    for (int tile = 0; tile < P1_NT; ++tile) {
        const int b = tile & 1;
        char* KH = sm1 + P1_KH + b * 9216;
        char* KL = sm1 + P1_KL + b * 9216;
        char* VH = sm1 + P1_VH + b * 9216;
        char* VL = sm1 + P1_VL + b * 9216;
#pragma unroll
        for (int j = 0; j < 4; ++j) {
            const int sr = rbase + 16 * j;
            unsigned h0, l0_, h1, l1;
            float fx = featmap(bk[j].x), fy = featmap(bk[j].y);
            float fz = featmap(bk[j].z), fw = featmap(bk[j].w);
            ksum4.x += fx; ksum4.y += fy; ksum4.z += fz; ksum4.w += fw;
            bsplit2(fx, fy, h0, l0_);
            bsplit2(fz, fw, h1, l1);
            *(u64*)(KH + sr * 144 + c4 * 8) = ((u64)h1 << 32) | h0;
            *(u64*)(KL + sr * 144 + c4 * 8) = ((u64)l1 << 32) | l0_;
            bsplit2(bv[j].x, bv[j].y, h0, l0_);
            bsplit2(bv[j].z, bv[j].w, h1, l1);
            *(u64*)(VH + sr * 144 + c4 * 8) = ((u64)h1 << 32) | h0;
            *(u64*)(VL + sr * 144 + c4 * 8) = ((u64)l1 << 32) | l0_;
        }
        __syncthreads();

        if (tile + 1 < P1_NT) {
#pragma unroll
            for (int j = 0; j < 4; ++j) {
                size_t row = (size_t)(n * Ss + s0 + (tile + 1) * 64 + rbase + 16 * j);
                bk[j] = *(const float4*)(keys   + row * ROWSTRIDE + h * Dd + c4 * 4);
                bv[j] = *(const float4*)(values + row * ROWSTRIDE + h * Dd + c4 * 4);
            }
        }

        const uint32_t KHu = smb + P1_KH + b * 9216;
        const uint32_t KLu = smb + P1_KL + b * 9216;
        const uint32_t VHu = smb + P1_VH + b * 9216;
        const uint32_t VLu = smb + P1_VL + b * 9216;
#pragma unroll
        for (int k2 = 0; k2 < 2; ++k2) {
            const int kt = ki * 2 + k2;
            uint32_t ah[2][4], al[2][4];
#pragma unroll
            for (int m2 = 0; m2 < 2; ++m2) {
                const int mt = mi * 2 + m2;   // e-tile
                ldm4t(ah[m2], VHu + (uint32_t)(kt * 2304 + mt * 32) + aoff);
                ldm4t(al[m2], VLu + (uint32_t)(kt * 2304 + mt * 32) + aoff);
            }
#pragma unroll
            for (int g2 = 0; g2 < 4; ++g2) {
                const int gx = ni * 4 + g2;   // d-group (full coverage)
                uint32_t bh[2], bl[2];
                ldm2t(bh, KHu + (uint32_t)(kt * 2304 + gx * 16) + boff);
                ldm2t(bl, KLu + (uint32_t)(kt * 2304 + gx * 16) + boff);
#pragma unroll
                for (int m2 = 0; m2 < 2; ++m2) {
                    mma_bf16(acc[m2][g2], ah[m2], bh[0], bh[1]);
                    mma_bf16(acc[m2][g2], ah[m2], bl[0], bl[1]);
                    mma_bf16(acc[m2][g2], al[m2], bh[0], bh[1]);
                }
            }
        }
    }

    // ---- combine k-split pairs via smem; Ksum tree (dead-buffer scratch) ----
    __syncthreads();
    float* S    = (float*)(sm1 + P1_KH);      // 16 KB combine scratch
    float* scrK = (float*)(sm1 + P1_VH);      // 16x68 ksum scratch
    if (ki == 1) {
        const int j = wid >> 1;
#pragma unroll
        for (int m2 = 0; m2 < 2; ++m2)
#pragma unroll
            for (int g2 = 0; g2 < 4; ++g2) {
                const int cell = m2 * 4 + g2;
                *(float4*)(S + ((cell * 4 + j) * 32 + lid) * 4) = acc[m2][g2];
            }
    }
    *(float4*)(scrK + rbase * 68 + c4 * 4) = ksum4;
    __syncthreads();

    if (t < 64) {
        float s = 0.f;
#pragma unroll
        for (int r = 0; r < 16; ++r) s += scrK[r * 68 + t];
        g_part_ks[(blockIdx.x * NH + nh) * 64 + t] = s;
    }
    if (ki == 0) {
        const int j = wid >> 1;
        float* base = g_part_kv + ((size_t)blockIdx.x * NH + nh) * 4096;
#pragma unroll
        for (int m2 = 0; m2 < 2; ++m2)
#pragma unroll
            for (int g2 = 0; g2 < 4; ++g2) {
                const int cell = m2 * 4 + g2;
                float4 o = *(float4*)(S + ((cell * 4 + j) * 32 + lid) * 4);
                o.x += acc[m2][g2].x; o.y += acc[m2][g2].y;
                o.z += acc[m2][g2].z; o.w += acc[m2][g2].w;
                const int e0 = (mi * 2 + m2) * 16 + qg;
                const int d0 = (ni * 4 + g2) * 8 + tg * 2;
                *(float2*)(base + e0 * 64 + d0)       = make_float2(o.x, o.y);
                *(float2*)(base + (e0 + 8) * 64 + d0) = make_float2(o.z, o.w);
            }
    }
}

// ============================================================================
// Phase 1b: fixed-order reduction (16 slots)
// ============================================================================
__global__ void reduce_kernel() {
    int i = blockIdx.x * 256 + threadIdx.x;
    if (i < NH * 1024) {
        float4 s = make_float4(0.f, 0.f, 0.f, 0.f);
#pragma unroll
        for (int c = 0; c < P1_CHUNKS; c++) {
            float4 p = *(const float4*)(g_part_kv + (size_t)c * NH * 4096 + i * 4);
            s.x += p.x; s.y += p.y; s.z += p.z; s.w += p.w;
        }
        *(float4*)(g_kv + i * 4) = s;
    } else if (i < NH * 1024 + NH * 16) {
        int j = i - NH * 1024;
        float4 s = make_float4(0.f, 0.f, 0.f, 0.f);
#pragma unroll
        for (int c = 0; c < P1_CHUNKS; c++) {
            float4 p = *(const float4*)(g_part_ks + c * NH * 64 + j * 4);
            s.x += p.x; s.y += p.y; s.z += p.z; s.w += p.w;
        }
        *(float4*)(g_ks + j * 4) = s;
    }
}

// ---- p2 smem: B only (72 x 144B hi/lo) ----
constexpr uint32_t P2_BH = 0;
constexpr uint32_t P2_BL = 10368;
constexpr uint32_t P2_DSM = 20736;
constexpr int P2_TILES = 4;

// ============================================================================
// Phase 2: out = (phiQ @ KV_ext) * Z. 256 thr / 8 warps, warp = one m16
// l-tile, 9 n-tiles (Z = B row 64). A-fragments register-direct from gmem
// (coalesced float2). 4 l-tiles/CTA, UNROLLED rolling prefetch (static buffer
// indices -> no spills): tile t+1 loads issued before tile t's MMA.
// Grid (Ll/512, NH).
// ============================================================================
__global__ __launch_bounds__(256, 2) void p2_kernel(const float* __restrict__ queries,
                                                    float* __restrict__ out) {
    extern __shared__ __align__(16) char sm2[];
    char* BH = sm2 + P2_BH; char* BL = sm2 + P2_BL;

    const int t    = threadIdx.x;
    const int wid  = t >> 5, lane = t & 31;
    const int g    = lane >> 2, tg = lane & 3;
    const int nh   = blockIdx.y;
    const int n    = nh >> 3, h = nh & 7;
    const int lbase = blockIdx.x * (128 * P2_TILES);

    // stage B: rows 0..63 = g_kv[e][d], row 64 = g_ks (Ksum), 65..71 = 0
    if (t < 72) {
        const float* src = (t < 64) ? (g_kv + (size_t)nh * 4096 + t * 64)
                                    : (g_ks + nh * 64);
#pragma unroll
        for (int c = 0; c < 16; ++c) {
            float4 v = (t <= 64) ? *(const float4*)(src + c * 4)
                                 : make_float4(0.f, 0.f, 0.f, 0.f);
            unsigned hxy, lxy, hzw, lzw;
            bsplit2(v.x, v.y, hxy, lxy);
            bsplit2(v.z, v.w, hzw, lzw);
            *(u64*)(BH + t * 144 + c * 8) = ((u64)hzw << 32) | hxy;
            *(u64*)(BL + t * 144 + c * 8) = ((u64)lzw << 32) | lxy;
        }
    }

    const int r0 = wid * 16 + g;
    const float* qb = queries + ((size_t)(n * Ll + lbase) * ROWSTRIDE + h * Dd);

    float2 q[2][16];
    // prefetch tile 0 into buffer 0
    {
        const float* rowp = qb + (size_t)r0 * ROWSTRIDE;
#pragma unroll
        for (int kt = 0; kt < 4; ++kt) {
            const int col = kt * 16 + tg * 2;
            q[0][kt * 4 + 0] = *(const float2*)(rowp + col);
            q[0][kt * 4 + 1] = *(const float2*)(rowp + 8 * ROWSTRIDE + col);
            q[0][kt * 4 + 2] = *(const float2*)(rowp + col + 8);
            q[0][kt * 4 + 3] = *(const float2*)(rowp + 8 * ROWSTRIDE + col + 8);
        }
    }
    __syncthreads();   // B staged

#pragma unroll
    for (int tile = 0; tile < P2_TILES; ++tile) {
        const int cur = tile & 1;          // compile-time after unroll
        // rolling prefetch into the other buffer (static index)
        if (tile + 1 < P2_TILES) {
            const float* rowp = qb + (size_t)((tile + 1) * 128 + r0) * ROWSTRIDE;
#pragma unroll
            for (int kt = 0; kt < 4; ++kt) {
                const int col = kt * 16 + tg * 2;
                q[cur ^ 1][kt * 4 + 0] = *(const float2*)(rowp + col);
                q[cur ^ 1][kt * 4 + 1] = *(const float2*)(rowp + 8 * ROWSTRIDE + col);
                q[cur ^ 1][kt * 4 + 2] = *(const float2*)(rowp + col + 8);
                q[cur ^ 1][kt * 4 + 3] = *(const float2*)(rowp + 8 * ROWSTRIDE + col + 8);
            }
        }

        float4 C[9];
#pragma unroll
        for (int nt = 0; nt < 9; ++nt) C[nt] = make_float4(0.f, 0.f, 0.f, 0.f);

#pragma unroll
        for (int kt = 0; kt < 4; ++kt) {
            uint32_t ah[4], al[4];
#pragma unroll
            for (int j = 0; j < 4; ++j) {
                float2 v = q[cur][kt * 4 + j];
                bsplit2(featmap(v.x), featmap(v.y), ah[j], al[j]);
            }
            const int kb = kt * 32 + tg * 4;
#pragma unroll
            for (int nt = 0; nt < 9; ++nt) {
                const int e0 = nt * 8 + g;
                uint32_t bh0 = *(const uint32_t*)(BH + e0 * 144 + kb);
                uint32_t bh1 = *(const uint32_t*)(BH + e0 * 144 + kb + 16);
                uint32_t bl0 = *(const uint32_t*)(BL + e0 * 144 + kb);
                uint32_t bl1 = *(const uint32_t*)(BL + e0 * 144 + kb + 16);
                mma_bf16(C[nt], ah, bh0, bh1);
                mma_bf16(C[nt], ah, bl0, bl1);
                mma_bf16(C[nt], al, bh0, bh1);
            }
        }

        // epilogue: Z = C[8] col 0 (quad-leader lanes)
        const int src = (lane >> 2) << 2;
        float z0 = __shfl_sync(0xFFFFFFFFu, C[8].x, src);
        float z1 = __shfl_sync(0xFFFFFFFFu, C[8].z, src);
        float i0 = 1.0f / (z0 + 1e-6f);
        float i1 = 1.0f / (z1 + 1e-6f);
        const int row = lbase + tile * 128 + r0;
        float* p0 = out + ((size_t)(n * Ll + row) * Hh + h) * Dd;
        float* p1 = p0 + (size_t)8 * ROWSTRIDE;
#pragma unroll
        for (int nt = 0; nt < 8; ++nt) {
            const int col = nt * 8 + tg * 2;
            *(float2*)(p0 + col) = make_float2(C[nt].x * i0, C[nt].y * i0);
            *(float2*)(p1 + col) = make_float2(C[nt].z * i1, C[nt].w * i1);
        }
    }
}

// ============================================================================
extern "C" void kernel_launch(void* const* d_in, const int* in_sizes, int n_in,
                              void* d_out, int out_size) {
    const float* q = (const float*)d_in[0];
    const float* k = (const float*)d_in[1];
    const float* v = (const float*)d_in[2];
    float* o = (float*)d_out;
    (void)in_sizes; (void)n_in; (void)out_size;

    cudaFuncSetAttribute(p1_kernel, cudaFuncAttributeMaxDynamicSharedMemorySize, P1_DSM);
    cudaFuncSetAttribute(p2_kernel, cudaFuncAttributeMaxDynamicSharedMemorySize, P2_DSM);

    p1_kernel<<<dim3(P1_CHUNKS, NH), 256, P1_DSM>>>(k, v);
    reduce_kernel<<<(NH * 1024 + NH * 16 + 255) / 256, 256>>>();
    p2_kernel<<<dim3(Ll / (128 * P2_TILES), NH), 256, P2_DSM>>>(q, o);
}

// round 16
// speedup vs baseline: 1.1250x; 1.0676x over previous
#include <cuda_runtime.h>
#include <cuda_bf16.h>
#include <cstdint>

// LinearAttention: out[n,l,h,e] = (phi(Q)@KV) * Z, phi = elu+1 (vlen cancels)
//   KV = sum_s phi(K)[s,d] * V[s,e] ;  Z = 1/(phi(Q).Ksum + 1e-6)
//
// R16 = R13 (best measured: p1 38.7, p2 43.7) with B-operand production moved
// into the reduce kernel: reduce emits pre-split bf16 hi/lo B (KV rows + Ksum
// row 64 + zero rows 65..71) in p2's exact 144B-pitch layout, so p2's
// B-staging is a pure linear copy by all 256 threads.

#define DEV_INLINE __device__ __forceinline__

constexpr int Hh = 8, Dd = 64, Ll = 8192, Ss = 8192, Nn = 4;
constexpr int NH = Nn * Hh;                // 32
constexpr int ROWSTRIDE = Hh * Dd;         // 512
constexpr int P1_CHUNKS = 16;
constexpr int P1_SCHUNK = Ss / P1_CHUNKS;  // 512 s per CTA (8 tiles of 64)
constexpr int P1_NT = P1_SCHUNK / 64;      // 8

__device__ __align__(16) float g_part_kv[(size_t)P1_CHUNKS * NH * 4096]; // [e][d]
__device__ __align__(16) float g_part_ks[P1_CHUNKS * NH * 64];

using u64 = unsigned long long;

// pre-split B operand: [nh][72 rows][16 u64] (row = e / Ksum / pad, col = d)
__device__ __align__(16) u64 g_bh[NH * 72 * 16];
__device__ __align__(16) u64 g_bl[NH * 72 * 16];

DEV_INLINE float featmap(float x) { return __expf(fminf(x, 0.f)) + fmaxf(x, 0.f); }
DEV_INLINE unsigned bf2u(__nv_bfloat162 v) { return *reinterpret_cast<unsigned*>(&v); }
DEV_INLINE void bsplit2(float a, float b, unsigned& h, unsigned& l) {
    __nv_bfloat162 hv = __floats2bfloat162_rn(a, b);
    float2 hf = __bfloat1622float2(hv);
    __nv_bfloat162 lv = __floats2bfloat162_rn(a - hf.x, b - hf.y);
    h = bf2u(hv); l = bf2u(lv);
}
DEV_INLINE uint32_t smem_u32(const void* p) {
    uint32_t a;
    asm("{ .reg .u64 t; cvta.to.shared.u64 t, %1; cvt.u32.u64 %0, t; }"
        : "=r"(a) : "l"(p));
    return a;
}
DEV_INLINE void mma_bf16(float4& c, const uint32_t a[4], uint32_t b0, uint32_t b1) {
    asm volatile(
        "mma.sync.aligned.m16n8k16.row.col.f32.bf16.bf16.f32 "
        "{%0,%1,%2,%3}, {%4,%5,%6,%7}, {%8,%9}, {%0,%1,%2,%3};"
        : "+f"(c.x), "+f"(c.y), "+f"(c.z), "+f"(c.w)
        : "r"(a[0]), "r"(a[1]), "r"(a[2]), "r"(a[3]), "r"(b0), "r"(b1));
}
DEV_INLINE void ldm4t(uint32_t* r, uint32_t addr) {
    asm volatile(
        "ldmatrix.sync.aligned.m8n8.x4.trans.shared.b16 {%0,%1,%2,%3}, [%4];"
        : "=r"(r[0]), "=r"(r[1]), "=r"(r[2]), "=r"(r[3]) : "r"(addr));
}
DEV_INLINE void ldm2t(uint32_t* r, uint32_t addr) {
    asm volatile(
        "ldmatrix.sync.aligned.m8n8.x2.trans.shared.b16 {%0,%1}, [%2];"
        : "=r"(r[0]), "=r"(r[1]) : "r"(addr));
}

// ---- p1 smem: K/V hi/lo, each 2buf x 64 x 144B ----
constexpr uint32_t P1_KH = 0;
constexpr uint32_t P1_KL = 18432;
constexpr uint32_t P1_VH = 36864;
constexpr uint32_t P1_VL = 55296;
constexpr uint32_t P1_DSM = 73728;

// ============================================================================
// Phase 1 (R12/R13-validated, 38.7us): D[e][d] = V^T @ phiK. 256 thr / 8 warps.
// ============================================================================
__global__ __launch_bounds__(256) void p1_kernel(const float* __restrict__ keys,
                                                 const float* __restrict__ values) {
    extern __shared__ __align__(16) char sm1[];

    const int t   = threadIdx.x;
    const int wid = t >> 5, lid = t & 31;
    const int grp = lid >> 3, r8 = lid & 7;
    const int qg  = lid >> 2, tg = lid & 3;
    const int nh  = blockIdx.y;
    const int n   = nh >> 3, h = nh & 7;
    const int s0  = blockIdx.x * P1_SCHUNK;
    const int ki  = wid & 1, ni = (wid >> 1) & 1, mi = wid >> 2;

    const uint32_t smb = smem_u32(sm1);
    const uint32_t aoff = (uint32_t)((r8 + ((grp & 2) ? 8 : 0)) * 144 +
                                     ((grp & 1) ? 8 : 0) * 2);
    const uint32_t boff = (uint32_t)((r8 + ((grp & 1) ? 8 : 0)) * 144);

    float4 acc[2][4];
#pragma unroll
    for (int i = 0; i < 2; i++)
#pragma unroll
        for (int j = 0; j < 4; j++) acc[i][j] = make_float4(0.f, 0.f, 0.f, 0.f);
    float4 ksum4 = make_float4(0.f, 0.f, 0.f, 0.f);

    const int c4 = t & 15, rbase = t >> 4;

    float4 bk[4], bv[4];
#pragma unroll
    for (int j = 0; j < 4; ++j) {
        size_t row = (size_t)(n * Ss + s0 + rbase + 16 * j);
        bk[j] = *(const float4*)(keys   + row * ROWSTRIDE + h * Dd + c4 * 4);
        bv[j] = *(const float4*)(values + row * ROWSTRIDE + h * Dd + c4 * 4);
    }

    for (int tile = 0; tile < P1_NT; ++tile) {
        const int b = tile & 1;
        char* KH = sm1 + P1_KH + b * 9216;
        char* KL = sm1 + P1_KL + b * 9216;
        char* VH = sm1 + P1_VH + b * 9216;
        char* VL = sm1 + P1_VL + b * 9216;
#pragma unroll
        for (int j = 0; j < 4; ++j) {
            const int sr = rbase + 16 * j;
            unsigned h0, l0_, h1, l1;
            float fx = featmap(bk[j].x), fy = featmap(bk[j].y);
            float fz = featmap(bk[j].z), fw = featmap(bk[j].w);
            ksum4.x += fx; ksum4.y += fy; ksum4.z += fz; ksum4.w += fw;
            bsplit2(fx, fy, h0, l0_);
            bsplit2(fz, fw, h1, l1);
            *(u64*)(KH + sr * 144 + c4 * 8) = ((u64)h1 << 32) | h0;
            *(u64*)(KL + sr * 144 + c4 * 8) = ((u64)l1 << 32) | l0_;
            bsplit2(bv[j].x, bv[j].y, h0, l0_);
            bsplit2(bv[j].z, bv[j].w, h1, l1);
            *(u64*)(VH + sr * 144 + c4 * 8) = ((u64)h1 << 32) | h0;
            *(u64*)(VL + sr * 144 + c4 * 8) = ((u64)l1 << 32) | l0_;
        }
        __syncthreads();

        if (tile + 1 < P1_NT) {
#pragma unroll
            for (int j = 0; j < 4; ++j) {
                size_t row = (size_t)(n * Ss + s0 + (tile + 1) * 64 + rbase + 16 * j);
                bk[j] = *(const float4*)(keys   + row * ROWSTRIDE + h * Dd + c4 * 4);
                bv[j] = *(const float4*)(values + row * ROWSTRIDE + h * Dd + c4 * 4);
            }
        }

        const uint32_t KHu = smb + P1_KH + b * 9216;
        const uint32_t KLu = smb + P1_KL + b * 9216;
        const uint32_t VHu = smb + P1_VH + b * 9216;
        const uint32_t VLu = smb + P1_VL + b * 9216;
#pragma unroll
        for (int k2 = 0; k2 < 2; ++k2) {
            const int kt = ki * 2 + k2;
            uint32_t ah[2][4], al[2][4];
#pragma unroll
            for (int m2 = 0; m2 < 2; ++m2) {
                const int mt = mi * 2 + m2;   // e-tile
                ldm4t(ah[m2], VHu + (uint32_t)(kt * 2304 + mt * 32) + aoff);
                ldm4t(al[m2], VLu + (uint32_t)(kt * 2304 + mt * 32) + aoff);
            }
#pragma unroll
            for (int g2 = 0; g2 < 4; ++g2) {
                const int gx = ni * 4 + g2;   // d-group (full coverage)
                uint32_t bh[2], bl[2];
                ldm2t(bh, KHu + (uint32_t)(kt * 2304 + gx * 16) + boff);
                ldm2t(bl, KLu + (uint32_t)(kt * 2304 + gx * 16) + boff);
#pragma unroll
                for (int m2 = 0; m2 < 2; ++m2) {
                    mma_bf16(acc[m2][g2], ah[m2], bh[0], bh[1]);
                    mma_bf16(acc[m2][g2], ah[m2], bl[0], bl[1]);
                    mma_bf16(acc[m2][g2], al[m2], bh[0], bh[1]);
                }
            }
        }
    }

    // ---- combine k-split pairs via smem; Ksum tree (dead-buffer scratch) ----
    __syncthreads();
    float* S    = (float*)(sm1 + P1_KH);      // 16 KB combine scratch
    float* scrK = (float*)(sm1 + P1_VH);      // 16x68 ksum scratch
    if (ki == 1) {
        const int j = wid >> 1;
#pragma unroll
        for (int m2 = 0; m2 < 2; ++m2)
#pragma unroll
            for (int g2 = 0; g2 < 4; ++g2) {
                const int cell = m2 * 4 + g2;
                *(float4*)(S + ((cell * 4 + j) * 32 + lid) * 4) = acc[m2][g2];
            }
    }
    *(float4*)(scrK + rbase * 68 + c4 * 4) = ksum4;
    __syncthreads();

    if (t < 64) {
        float s = 0.f;
#pragma unroll
        for (int r = 0; r < 16; ++r) s += scrK[r * 68 + t];
        g_part_ks[(blockIdx.x * NH + nh) * 64 + t] = s;
    }
    if (ki == 0) {
        const int j = wid >> 1;
        float* base = g_part_kv + ((size_t)blockIdx.x * NH + nh) * 4096;
#pragma unroll
        for (int m2 = 0; m2 < 2; ++m2)
#pragma unroll
            for (int g2 = 0; g2 < 4; ++g2) {
                const int cell = m2 * 4 + g2;
                float4 o = *(float4*)(S + ((cell * 4 + j) * 32 + lid) * 4);
                o.x += acc[m2][g2].x; o.y += acc[m2][g2].y;
                o.z += acc[m2][g2].z; o.w += acc[m2][g2].w;
                const int e0 = (mi * 2 + m2) * 16 + qg;
                const int d0 = (ni * 4 + g2) * 8 + tg * 2;
                *(float2*)(base + e0 * 64 + d0)       = make_float2(o.x, o.y);
                *(float2*)(base + (e0 + 8) * 64 + d0) = make_float2(o.z, o.w);
            }
    }
}

// ============================================================================
// Phase 1b: fixed-order reduction -> pre-split bf16 B operand (g_bh/g_bl).
// Rows 0..63 = KV[e][d], row 64 = Ksum, rows 65..71 = 0. Layout: [nh][row][16 u64].
// ============================================================================
constexpr int RED_A = NH * 65 * 16;   // data rows
constexpr int RED_B = NH * 7 * 16;    // zero rows

__global__ void reduce_kernel() {
    int i = blockIdx.x * 256 + threadIdx.x;
    if (i < RED_A) {
        const int nh  = i / (65 * 16);
        const int rem = i % (65 * 16);
        const int row = rem >> 4, c4 = rem & 15;
        float4 s = make_float4(0.f, 0.f, 0.f, 0.f);
        if (row < 64) {
#pragma unroll
            for (int c = 0; c < P1_CHUNKS; c++) {
                float4 p = *(const float4*)(g_part_kv +
                    ((size_t)c * NH + nh) * 4096 + row * 64 + c4 * 4);
                s.x += p.x; s.y += p.y; s.z += p.z; s.w += p.w;
            }
        } else {
#pragma unroll
            for (int c = 0; c < P1_CHUNKS; c++) {
                float4 p = *(const float4*)(g_part_ks + (c * NH + nh) * 64 + c4 * 4);
                s.x += p.x; s.y += p.y; s.z += p.z; s.w += p.w;
            }
        }
        unsigned hxy, lxy, hzw, lzw;
        bsplit2(s.x, s.y, hxy, lxy);
        bsplit2(s.z, s.w, hzw, lzw);
        const size_t o = (size_t)(nh * 72 + row) * 16 + c4;
        g_bh[o] = ((u64)hzw << 32) | hxy;
        g_bl[o] = ((u64)lzw << 32) | lxy;
    } else if (i < RED_A + RED_B) {
        const int j   = i - RED_A;
        const int nh  = j / (7 * 16);
        const int rem = j % (7 * 16);
        const int row = 65 + (rem >> 4), c4 = rem & 15;
        const size_t o = (size_t)(nh * 72 + row) * 16 + c4;
        g_bh[o] = 0ull;
        g_bl[o] = 0ull;
    }
}

// ---- p2 smem: B only (72 x 144B hi/lo) ----
constexpr uint32_t P2_BH = 0;
constexpr uint32_t P2_BL = 10368;
constexpr uint32_t P2_DSM = 20736;

// ============================================================================
// Phase 2 (R13-validated, 43.7us): out = (phiQ @ KV_ext) * Z. 256 thr /
// 8 warps, warp = one m16 l-tile, 9 n-tiles (Z = B row 64). A-fragments
// register-direct from gmem; B staged by pure linear copy of pre-split
// g_bh/g_bl. 2 l-tiles per CTA, both prefetched. Grid (Ll/256, NH).
// ============================================================================
__global__ __launch_bounds__(256, 2) void p2_kernel(const float* __restrict__ queries,
                                                    float* __restrict__ out) {
    extern __shared__ __align__(16) char sm2[];
    char* BH = sm2 + P2_BH; char* BL = sm2 + P2_BL;

    const int t    = threadIdx.x;
    const int wid  = t >> 5, lane = t & 31;
    const int g    = lane >> 2, tg = lane & 3;
    const int nh   = blockIdx.y;
    const int n    = nh >> 3, h = nh & 7;
    const int lbase = blockIdx.x * 256;

    // stage B: pure linear copy (all 256 threads; rows pre-split by reduce)
    {
        const u64* bhs = g_bh + (size_t)nh * 72 * 16;
        const u64* bls = g_bl + (size_t)nh * 72 * 16;
#pragma unroll
        for (int k = 0; k < 5; ++k) {
            int idx = t + 256 * k;
            if (idx < 72 * 16) {
                int row = idx >> 4, c = idx & 15;
                *(u64*)(BH + row * 144 + c * 8) = bhs[idx];
                *(u64*)(BL + row * 144 + c * 8) = bls[idx];
            }
        }
    }

    // raw Q fragment loads for BOTH tiles (A-frag layout == coalesced float2)
    const int r0 = wid * 16 + g;
    const float* qb = queries + ((size_t)(n * Ll + lbase) * ROWSTRIDE + h * Dd);
    float2 q[2][16];
#pragma unroll
    for (int tile = 0; tile < 2; ++tile) {
        const float* rowp = qb + (size_t)(tile * 128 + r0) * ROWSTRIDE;
#pragma unroll
        for (int kt = 0; kt < 4; ++kt) {
            const int col = kt * 16 + tg * 2;
            q[tile][kt * 4 + 0] = *(const float2*)(rowp + col);
            q[tile][kt * 4 + 1] = *(const float2*)(rowp + 8 * ROWSTRIDE + col);
            q[tile][kt * 4 + 2] = *(const float2*)(rowp + col + 8);
            q[tile][kt * 4 + 3] = *(const float2*)(rowp + 8 * ROWSTRIDE + col + 8);
        }
    }
    __syncthreads();   // B staged

#pragma unroll
    for (int tile = 0; tile < 2; ++tile) {
        float4 C[9];
#pragma unroll
        for (int nt = 0; nt < 9; ++nt) C[nt] = make_float4(0.f, 0.f, 0.f, 0.f);

#pragma unroll
        for (int kt = 0; kt < 4; ++kt) {
            uint32_t ah[4], al[4];
#pragma unroll
            for (int j = 0; j < 4; ++j) {
                float2 v = q[tile][kt * 4 + j];
                bsplit2(featmap(v.x), featmap(v.y), ah[j], al[j]);
            }
            const int kb = kt * 32 + tg * 4;
#pragma unroll
            for (int nt = 0; nt < 9; ++nt) {
                const int e0 = nt * 8 + g;
                uint32_t bh0 = *(const uint32_t*)(BH + e0 * 144 + kb);
                uint32_t bh1 = *(const uint32_t*)(BH + e0 * 144 + kb + 16);
                uint32_t bl0 = *(const uint32_t*)(BL + e0 * 144 + kb);
                uint32_t bl1 = *(const uint32_t*)(BL + e0 * 144 + kb + 16);
                mma_bf16(C[nt], ah, bh0, bh1);
                mma_bf16(C[nt], ah, bl0, bl1);
                mma_bf16(C[nt], al, bh0, bh1);
            }
        }

        // epilogue: Z = C[8] col 0 (quad-leader lanes)
        const int src = (lane >> 2) << 2;
        float z0 = __shfl_sync(0xFFFFFFFFu, C[8].x, src);
        float z1 = __shfl_sync(0xFFFFFFFFu, C[8].z, src);
        float i0 = 1.0f / (z0 + 1e-6f);
        float i1 = 1.0f / (z1 + 1e-6f);
        const int row = lbase + tile * 128 + r0;
        float* p0 = out + ((size_t)(n * Ll + row) * Hh + h) * Dd;
        float* p1 = p0 + (size_t)8 * ROWSTRIDE;
#pragma unroll
        for (int nt = 0; nt < 8; ++nt) {
            const int col = nt * 8 + tg * 2;
            *(float2*)(p0 + col) = make_float2(C[nt].x * i0, C[nt].y * i0);
            *(float2*)(p1 + col) = make_float2(C[nt].z * i1, C[nt].w * i1);
        }
    }
}

// ============================================================================
extern "C" void kernel_launch(void* const* d_in, const int* in_sizes, int n_in,
                              void* d_out, int out_size) {
    const float* q = (const float*)d_in[0];
    const float* k = (const float*)d_in[1];
    const float* v = (const float*)d_in[2];
    float* o = (float*)d_out;
    (void)in_sizes; (void)n_in; (void)out_size;

    cudaFuncSetAttribute(p1_kernel, cudaFuncAttributeMaxDynamicSharedMemorySize, P1_DSM);
    cudaFuncSetAttribute(p2_kernel, cudaFuncAttributeMaxDynamicSharedMemorySize, P2_DSM);

    p1_kernel<<<dim3(P1_CHUNKS, NH), 256, P1_DSM>>>(k, v);
    reduce_kernel<<<(RED_A + RED_B + 255) / 256, 256>>>();
    p2_kernel<<<dim3(Ll / 256, NH), 256, P2_DSM>>>(q, o);
}

// round 17
// speedup vs baseline: 1.1496x; 1.0219x over previous
#include <cuda_runtime.h>
#include <cuda_bf16.h>
#include <cstdint>

// LinearAttention: out[n,l,h,e] = (phi(Q)@KV) * Z, phi = elu+1 (vlen cancels)
//   KV = sum_s phi(K)[s,d] * V[s,e] ;  Z = 1/(phi(Q).Ksum + 1e-6)
//
// R17 = R16 (measured 82.0us) with P1_CHUNKS 16->8: p1 becomes a single
// 2-CTA/SM wave (256 CTAs) and partial-KV traffic halves (reduce reads too).
// Everything else identical to the validated R16.

#define DEV_INLINE __device__ __forceinline__

constexpr int Hh = 8, Dd = 64, Ll = 8192, Ss = 8192, Nn = 4;
constexpr int NH = Nn * Hh;                // 32
constexpr int ROWSTRIDE = Hh * Dd;         // 512
constexpr int P1_CHUNKS = 8;
constexpr int P1_SCHUNK = Ss / P1_CHUNKS;  // 1024 s per CTA (16 tiles of 64)
constexpr int P1_NT = P1_SCHUNK / 64;      // 16

__device__ __align__(16) float g_part_kv[(size_t)P1_CHUNKS * NH * 4096]; // [e][d]
__device__ __align__(16) float g_part_ks[P1_CHUNKS * NH * 64];

using u64 = unsigned long long;

// pre-split B operand: [nh][72 rows][16 u64] (row = e / Ksum / pad, col = d)
__device__ __align__(16) u64 g_bh[NH * 72 * 16];
__device__ __align__(16) u64 g_bl[NH * 72 * 16];

DEV_INLINE float featmap(float x) { return __expf(fminf(x, 0.f)) + fmaxf(x, 0.f); }
DEV_INLINE unsigned bf2u(__nv_bfloat162 v) { return *reinterpret_cast<unsigned*>(&v); }
DEV_INLINE void bsplit2(float a, float b, unsigned& h, unsigned& l) {
    __nv_bfloat162 hv = __floats2bfloat162_rn(a, b);
    float2 hf = __bfloat1622float2(hv);
    __nv_bfloat162 lv = __floats2bfloat162_rn(a - hf.x, b - hf.y);
    h = bf2u(hv); l = bf2u(lv);
}
DEV_INLINE uint32_t smem_u32(const void* p) {
    uint32_t a;
    asm("{ .reg .u64 t; cvta.to.shared.u64 t, %1; cvt.u32.u64 %0, t; }"
        : "=r"(a) : "l"(p));
    return a;
}
DEV_INLINE void mma_bf16(float4& c, const uint32_t a[4], uint32_t b0, uint32_t b1) {
    asm volatile(
        "mma.sync.aligned.m16n8k16.row.col.f32.bf16.bf16.f32 "
        "{%0,%1,%2,%3}, {%4,%5,%6,%7}, {%8,%9}, {%0,%1,%2,%3};"
        : "+f"(c.x), "+f"(c.y), "+f"(c.z), "+f"(c.w)
        : "r"(a[0]), "r"(a[1]), "r"(a[2]), "r"(a[3]), "r"(b0), "r"(b1));
}
DEV_INLINE void ldm4t(uint32_t* r, uint32_t addr) {
    asm volatile(
        "ldmatrix.sync.aligned.m8n8.x4.trans.shared.b16 {%0,%1,%2,%3}, [%4];"
        : "=r"(r[0]), "=r"(r[1]), "=r"(r[2]), "=r"(r[3]) : "r"(addr));
}
DEV_INLINE void ldm2t(uint32_t* r, uint32_t addr) {
    asm volatile(
        "ldmatrix.sync.aligned.m8n8.x2.trans.shared.b16 {%0,%1}, [%2];"
        : "=r"(r[0]), "=r"(r[1]) : "r"(addr));
}

// ---- p1 smem: K/V hi/lo, each 2buf x 64 x 144B ----
constexpr uint32_t P1_KH = 0;
constexpr uint32_t P1_KL = 18432;
constexpr uint32_t P1_VH = 36864;
constexpr uint32_t P1_VL = 55296;
constexpr uint32_t P1_DSM = 73728;

// ============================================================================
// Phase 1 (R12/R13/R16-validated): D[e][d] = V^T @ phiK. 256 thr / 8 warps.
// wid: ki=wid&1, ni=(wid>>1)&1, mi=wid>>2. Cells: 2m x 4g. Grid (8, NH).
// ============================================================================
__global__ __launch_bounds__(256) void p1_kernel(const float* __restrict__ keys,
                                                 const float* __restrict__ values) {
    extern __shared__ __align__(16) char sm1[];

    const int t   = threadIdx.x;
    const int wid = t >> 5, lid = t & 31;
    const int grp = lid >> 3, r8 = lid & 7;
    const int qg  = lid >> 2, tg = lid & 3;
    const int nh  = blockIdx.y;
    const int n   = nh >> 3, h = nh & 7;
    const int s0  = blockIdx.x * P1_SCHUNK;
    const int ki  = wid & 1, ni = (wid >> 1) & 1, mi = wid >> 2;

    const uint32_t smb = smem_u32(sm1);
    const uint32_t aoff = (uint32_t)((r8 + ((grp & 2) ? 8 : 0)) * 144 +
                                     ((grp & 1) ? 8 : 0) * 2);
    const uint32_t boff = (uint32_t)((r8 + ((grp & 1) ? 8 : 0)) * 144);

    float4 acc[2][4];
#pragma unroll
    for (int i = 0; i < 2; i++)
#pragma unroll
        for (int j = 0; j < 4; j++) acc[i][j] = make_float4(0.f, 0.f, 0.f, 0.f);
    float4 ksum4 = make_float4(0.f, 0.f, 0.f, 0.f);

    const int c4 = t & 15, rbase = t >> 4;

    float4 bk[4], bv[4];
#pragma unroll
    for (int j = 0; j < 4; ++j) {
        size_t row = (size_t)(n * Ss + s0 + rbase + 16 * j);
        bk[j] = *(const float4*)(keys   + row * ROWSTRIDE + h * Dd + c4 * 4);
        bv[j] = *(const float4*)(values + row * ROWSTRIDE + h * Dd + c4 * 4);
    }

    for (int tile = 0; tile < P1_NT; ++tile) {
        const int b = tile & 1;
        char* KH = sm1 + P1_KH + b * 9216;
        char* KL = sm1 + P1_KL + b * 9216;
        char* VH = sm1 + P1_VH + b * 9216;
        char* VL = sm1 + P1_VL + b * 9216;
#pragma unroll
        for (int j = 0; j < 4; ++j) {
            const int sr = rbase + 16 * j;
            unsigned h0, l0_, h1, l1;
            float fx = featmap(bk[j].x), fy = featmap(bk[j].y);
            float fz = featmap(bk[j].z), fw = featmap(bk[j].w);
            ksum4.x += fx; ksum4.y += fy; ksum4.z += fz; ksum4.w += fw;
            bsplit2(fx, fy, h0, l0_);
            bsplit2(fz, fw, h1, l1);
            *(u64*)(KH + sr * 144 + c4 * 8) = ((u64)h1 << 32) | h0;
            *(u64*)(KL + sr * 144 + c4 * 8) = ((u64)l1 << 32) | l0_;
            bsplit2(bv[j].x, bv[j].y, h0, l0_);
            bsplit2(bv[j].z, bv[j].w, h1, l1);
            *(u64*)(VH + sr * 144 + c4 * 8) = ((u64)h1 << 32) | h0;
            *(u64*)(VL + sr * 144 + c4 * 8) = ((u64)l1 << 32) | l0_;
        }
        __syncthreads();

        if (tile + 1 < P1_NT) {
#pragma unroll
            for (int j = 0; j < 4; ++j) {
                size_t row = (size_t)(n * Ss + s0 + (tile + 1) * 64 + rbase + 16 * j);
                bk[j] = *(const float4*)(keys   + row * ROWSTRIDE + h * Dd + c4 * 4);
                bv[j] = *(const float4*)(values + row * ROWSTRIDE + h * Dd + c4 * 4);
            }
        }

        const uint32_t KHu = smb + P1_KH + b * 9216;
        const uint32_t KLu = smb + P1_KL + b * 9216;
        const uint32_t VHu = smb + P1_VH + b * 9216;
        const uint32_t VLu = smb + P1_VL + b * 9216;
#pragma unroll
        for (int k2 = 0; k2 < 2; ++k2) {
            const int kt = ki * 2 + k2;
            uint32_t ah[2][4], al[2][4];
#pragma unroll
            for (int m2 = 0; m2 < 2; ++m2) {
                const int mt = mi * 2 + m2;   // e-tile
                ldm4t(ah[m2], VHu + (uint32_t)(kt * 2304 + mt * 32) + aoff);
                ldm4t(al[m2], VLu + (uint32_t)(kt * 2304 + mt * 32) + aoff);
            }
#pragma unroll
            for (int g2 = 0; g2 < 4; ++g2) {
                const int gx = ni * 4 + g2;   // d-group (full coverage)
                uint32_t bh[2], bl[2];
                ldm2t(bh, KHu + (uint32_t)(kt * 2304 + gx * 16) + boff);
                ldm2t(bl, KLu + (uint32_t)(kt * 2304 + gx * 16) + boff);
#pragma unroll
                for (int m2 = 0; m2 < 2; ++m2) {
                    mma_bf16(acc[m2][g2], ah[m2], bh[0], bh[1]);
                    mma_bf16(acc[m2][g2], ah[m2], bl[0], bl[1]);
                    mma_bf16(acc[m2][g2], al[m2], bh[0], bh[1]);
                }
            }
        }
    }

    // ---- combine k-split pairs via smem; Ksum tree (dead-buffer scratch) ----
    __syncthreads();
    float* S    = (float*)(sm1 + P1_KH);      // 16 KB combine scratch
    float* scrK = (float*)(sm1 + P1_VH);      // 16x68 ksum scratch
    if (ki == 1) {
        const int j = wid >> 1;
#pragma unroll
        for (int m2 = 0; m2 < 2; ++m2)
#pragma unroll
            for (int g2 = 0; g2 < 4; ++g2) {
                const int cell = m2 * 4 + g2;
                *(float4*)(S + ((cell * 4 + j) * 32 + lid) * 4) = acc[m2][g2];
            }
    }
    *(float4*)(scrK + rbase * 68 + c4 * 4) = ksum4;
    __syncthreads();

    if (t < 64) {
        float s = 0.f;
#pragma unroll
        for (int r = 0; r < 16; ++r) s += scrK[r * 68 + t];
        g_part_ks[(blockIdx.x * NH + nh) * 64 + t] = s;
    }
    if (ki == 0) {
        const int j = wid >> 1;
        float* base = g_part_kv + ((size_t)blockIdx.x * NH + nh) * 4096;
#pragma unroll
        for (int m2 = 0; m2 < 2; ++m2)
#pragma unroll
            for (int g2 = 0; g2 < 4; ++g2) {
                const int cell = m2 * 4 + g2;
                float4 o = *(float4*)(S + ((cell * 4 + j) * 32 + lid) * 4);
                o.x += acc[m2][g2].x; o.y += acc[m2][g2].y;
                o.z += acc[m2][g2].z; o.w += acc[m2][g2].w;
                const int e0 = (mi * 2 + m2) * 16 + qg;
                const int d0 = (ni * 4 + g2) * 8 + tg * 2;
                *(float2*)(base + e0 * 64 + d0)       = make_float2(o.x, o.y);
                *(float2*)(base + (e0 + 8) * 64 + d0) = make_float2(o.z, o.w);
            }
    }
}

// ============================================================================
// Phase 1b: fixed-order reduction -> pre-split bf16 B operand (g_bh/g_bl).
// Rows 0..63 = KV[e][d], row 64 = Ksum, rows 65..71 = 0. Layout: [nh][row][16 u64].
// ============================================================================
constexpr int RED_A = NH * 65 * 16;   // data rows
constexpr int RED_B = NH * 7 * 16;    // zero rows

__global__ void reduce_kernel() {
    int i = blockIdx.x * 256 + threadIdx.x;
    if (i < RED_A) {
        const int nh  = i / (65 * 16);
        const int rem = i % (65 * 16);
        const int row = rem >> 4, c4 = rem & 15;
        float4 s = make_float4(0.f, 0.f, 0.f, 0.f);
        if (row < 64) {
#pragma unroll
            for (int c = 0; c < P1_CHUNKS; c++) {
                float4 p = *(const float4*)(g_part_kv +
                    ((size_t)c * NH + nh) * 4096 + row * 64 + c4 * 4);
                s.x += p.x; s.y += p.y; s.z += p.z; s.w += p.w;
            }
        } else {
#pragma unroll
            for (int c = 0; c < P1_CHUNKS; c++) {
                float4 p = *(const float4*)(g_part_ks + (c * NH + nh) * 64 + c4 * 4);
                s.x += p.x; s.y += p.y; s.z += p.z; s.w += p.w;
            }
        }
        unsigned hxy, lxy, hzw, lzw;
        bsplit2(s.x, s.y, hxy, lxy);
        bsplit2(s.z, s.w, hzw, lzw);
        const size_t o = (size_t)(nh * 72 + row) * 16 + c4;
        g_bh[o] = ((u64)hzw << 32) | hxy;
        g_bl[o] = ((u64)lzw << 32) | lxy;
    } else if (i < RED_A + RED_B) {
        const int j   = i - RED_A;
        const int nh  = j / (7 * 16);
        const int rem = j % (7 * 16);
        const int row = 65 + (rem >> 4), c4 = rem & 15;
        const size_t o = (size_t)(nh * 72 + row) * 16 + c4;
        g_bh[o] = 0ull;
        g_bl[o] = 0ull;
    }
}

// ---- p2 smem: B only (72 x 144B hi/lo) ----
constexpr uint32_t P2_BH = 0;
constexpr uint32_t P2_BL = 10368;
constexpr uint32_t P2_DSM = 20736;

// ============================================================================
// Phase 2 (R13/R16-validated): out = (phiQ @ KV_ext) * Z. 256 thr / 8 warps,
// warp = one m16 l-tile, 9 n-tiles (Z = B row 64). A-fragments register-
// direct from gmem; B staged by pure linear copy of pre-split g_bh/g_bl.
// 2 l-tiles per CTA, both prefetched. Grid (Ll/256, NH).
// ============================================================================
__global__ __launch_bounds__(256, 2) void p2_kernel(const float* __restrict__ queries,
                                                    float* __restrict__ out) {
    extern __shared__ __align__(16) char sm2[];
    char* BH = sm2 + P2_BH; char* BL = sm2 + P2_BL;

    const int t    = threadIdx.x;
    const int wid  = t >> 5, lane = t & 31;
    const int g    = lane >> 2, tg = lane & 3;
    const int nh   = blockIdx.y;
    const int n    = nh >> 3, h = nh & 7;
    const int lbase = blockIdx.x * 256;

    // stage B: pure linear copy (all 256 threads; rows pre-split by reduce)
    {
        const u64* bhs = g_bh + (size_t)nh * 72 * 16;
        const u64* bls = g_bl + (size_t)nh * 72 * 16;
#pragma unroll
        for (int k = 0; k < 5; ++k) {
            int idx = t + 256 * k;
            if (idx < 72 * 16) {
                int row = idx >> 4, c = idx & 15;
                *(u64*)(BH + row * 144 + c * 8) = bhs[idx];
                *(u64*)(BL + row * 144 + c * 8) = bls[idx];
            }
        }
    }

    // raw Q fragment loads for BOTH tiles (A-frag layout == coalesced float2)
    const int r0 = wid * 16 + g;
    const float* qb = queries + ((size_t)(n * Ll + lbase) * ROWSTRIDE + h * Dd);
    float2 q[2][16];
#pragma unroll
    for (int tile = 0; tile < 2; ++tile) {
        const float* rowp = qb + (size_t)(tile * 128 + r0) * ROWSTRIDE;
#pragma unroll
        for (int kt = 0; kt < 4; ++kt) {
            const int col = kt * 16 + tg * 2;
            q[tile][kt * 4 + 0] = *(const float2*)(rowp + col);
            q[tile][kt * 4 + 1] = *(const float2*)(rowp + 8 * ROWSTRIDE + col);
            q[tile][kt * 4 + 2] = *(const float2*)(rowp + col + 8);
            q[tile][kt * 4 + 3] = *(const float2*)(rowp + 8 * ROWSTRIDE + col + 8);
        }
    }
    __syncthreads();   // B staged

#pragma unroll
    for (int tile = 0; tile < 2; ++tile) {
        float4 C[9];
#pragma unroll
        for (int nt = 0; nt < 9; ++nt) C[nt] = make_float4(0.f, 0.f, 0.f, 0.f);

#pragma unroll
        for (int kt = 0; kt < 4; ++kt) {
            uint32_t ah[4], al[4];
#pragma unroll
            for (int j = 0; j < 4; ++j) {
                float2 v = q[tile][kt * 4 + j];
                bsplit2(featmap(v.x), featmap(v.y), ah[j], al[j]);
            }
            const int kb = kt * 32 + tg * 4;
#pragma unroll
            for (int nt = 0; nt < 9; ++nt) {
                const int e0 = nt * 8 + g;
                uint32_t bh0 = *(const uint32_t*)(BH + e0 * 144 + kb);
                uint32_t bh1 = *(const uint32_t*)(BH + e0 * 144 + kb + 16);
                uint32_t bl0 = *(const uint32_t*)(BL + e0 * 144 + kb);
                uint32_t bl1 = *(const uint32_t*)(BL + e0 * 144 + kb + 16);
                mma_bf16(C[nt], ah, bh0, bh1);
                mma_bf16(C[nt], ah, bl0, bl1);
                mma_bf16(C[nt], al, bh0, bh1);
            }
        }

        // epilogue: Z = C[8] col 0 (quad-leader lanes)
        const int src = (lane >> 2) << 2;
        float z0 = __shfl_sync(0xFFFFFFFFu, C[8].x, src);
        float z1 = __shfl_sync(0xFFFFFFFFu, C[8].z, src);
        float i0 = 1.0f / (z0 + 1e-6f);
        float i1 = 1.0f / (z1 + 1e-6f);
        const int row = lbase + tile * 128 + r0;
        float* p0 = out + ((size_t)(n * Ll + row) * Hh + h) * Dd;
        float* p1 = p0 + (size_t)8 * ROWSTRIDE;
#pragma unroll
        for (int nt = 0; nt < 8; ++nt) {
            const int col = nt * 8 + tg * 2;
            *(float2*)(p0 + col) = make_float2(C[nt].x * i0, C[nt].y * i0);
            *(float2*)(p1 + col) = make_float2(C[nt].z * i1, C[nt].w * i1);
        }
    }
}

// ============================================================================
extern "C" void kernel_launch(void* const* d_in, const int* in_sizes, int n_in,
                              void* d_out, int out_size) {
    const float* q = (const float*)d_in[0];
    const float* k = (const float*)d_in[1];
    const float* v = (const float*)d_in[2];
    float* o = (float*)d_out;
    (void)in_sizes; (void)n_in; (void)out_size;

    cudaFuncSetAttribute(p1_kernel, cudaFuncAttributeMaxDynamicSharedMemorySize, P1_DSM);
    cudaFuncSetAttribute(p2_kernel, cudaFuncAttributeMaxDynamicSharedMemorySize, P2_DSM);

    p1_kernel<<<dim3(P1_CHUNKS, NH), 256, P1_DSM>>>(k, v);
    reduce_kernel<<<(RED_A + RED_B + 255) / 256, 256>>>();
    p2_kernel<<<dim3(Ll / 256, NH), 256, P2_DSM>>>(q, o);
}